// round 1
// baseline (speedup 1.0000x reference)
#include <cuda_runtime.h>
#include <cstdint>

#define NNODES 40000
#define NGRAPHS 128
#define DD 128

// ---------------- scratch (no allocations allowed) ----------------
__device__ float g_t[(size_t)NNODES * DD];    // GEMM output (pre-aggregation)
__device__ float g_acc[(size_t)NNODES * DD];  // scatter accumulator
__device__ float g_h[(size_t)NNODES * DD];    // layer output (next-layer input)

// ---------------- GEMM: out[M,128] = A[M,128] @ W[128,128]^T ----------------
// Tile 128 rows x 128 cols per block, 256 threads, 8x8 microtile per thread.
// Smem holds K-transposed tiles so inner loop uses conflict-free LDS.128.
#define LDT 132
#define GEMM_SMEM (2 * 128 * LDT * sizeof(float))

__global__ __launch_bounds__(256) void gemm_kernel(
    const float* __restrict__ A, const float* __restrict__ W,
    float* __restrict__ out, int M)
{
    extern __shared__ float smem[];
    float* At = smem;              // At[k][r], k-major, padded row LDT
    float* Wt = smem + 128 * LDT;  // Wt[k][c]

    const int tid = threadIdx.x;
    const int rbase = blockIdx.x * 128;

    // Load + transpose tiles: 128x128 each = 4096 float4 loads -> 16 per thread
    #pragma unroll
    for (int rep = 0; rep < 16; rep++) {
        int idx = tid + rep * 256;        // 0..4095
        int r   = idx >> 5;               // 0..127 (row / out-feature)
        int kq  = idx & 31;               // 0..31  (k quad)
        float4 av = make_float4(0.f, 0.f, 0.f, 0.f);
        int gr = rbase + r;
        if (gr < M) av = *(const float4*)(A + (size_t)gr * DD + kq * 4);
        At[(kq * 4 + 0) * LDT + r] = av.x;
        At[(kq * 4 + 1) * LDT + r] = av.y;
        At[(kq * 4 + 2) * LDT + r] = av.z;
        At[(kq * 4 + 3) * LDT + r] = av.w;
        float4 wv = *(const float4*)(W + (size_t)r * DD + kq * 4); // r = out-feature c
        Wt[(kq * 4 + 0) * LDT + r] = wv.x;
        Wt[(kq * 4 + 1) * LDT + r] = wv.y;
        Wt[(kq * 4 + 2) * LDT + r] = wv.z;
        Wt[(kq * 4 + 3) * LDT + r] = wv.w;
    }
    __syncthreads();

    const int tx = tid & 15;   // col group
    const int ty = tid >> 4;   // row group

    float acc[8][8];
    #pragma unroll
    for (int i = 0; i < 8; i++)
        #pragma unroll
        for (int j = 0; j < 8; j++) acc[i][j] = 0.f;

    #pragma unroll 4
    for (int k = 0; k < 128; k++) {
        float4 a0 = *(const float4*)&At[k * LDT + ty * 8];
        float4 a1 = *(const float4*)&At[k * LDT + ty * 8 + 4];
        float4 b0 = *(const float4*)&Wt[k * LDT + tx * 8];
        float4 b1 = *(const float4*)&Wt[k * LDT + tx * 8 + 4];
        float a[8] = {a0.x, a0.y, a0.z, a0.w, a1.x, a1.y, a1.z, a1.w};
        float b[8] = {b0.x, b0.y, b0.z, b0.w, b1.x, b1.y, b1.z, b1.w};
        #pragma unroll
        for (int i = 0; i < 8; i++)
            #pragma unroll
            for (int j = 0; j < 8; j++)
                acc[i][j] = fmaf(a[i], b[j], acc[i][j]);
    }

    #pragma unroll
    for (int i = 0; i < 8; i++) {
        int gr = rbase + ty * 8 + i;
        if (gr < M) {
            float4 o0 = make_float4(acc[i][0], acc[i][1], acc[i][2], acc[i][3]);
            float4 o1 = make_float4(acc[i][4], acc[i][5], acc[i][6], acc[i][7]);
            *(float4*)(out + (size_t)gr * DD + tx * 8)     = o0;
            *(float4*)(out + (size_t)gr * DD + tx * 8 + 4) = o1;
        }
    }
}

// ---------------- scatter: acc[col[e]] += t[row[e]] * w[e] ----------------
// One warp per edge; lane i handles features [4i, 4i+4). Vector red (no return).
__device__ __forceinline__ void red_add_v4(float* dst, float4 v) {
    asm volatile("red.global.add.v4.f32 [%0], {%1, %2, %3, %4};"
                 :: "l"(dst), "f"(v.x), "f"(v.y), "f"(v.z), "f"(v.w)
                 : "memory");
}

__global__ __launch_bounds__(256) void scatter_kernel(
    const float* __restrict__ t, const int* __restrict__ rowp,
    const int* __restrict__ colp, const float* __restrict__ ew,
    float* __restrict__ acc, int E)
{
    int wid  = (blockIdx.x * blockDim.x + threadIdx.x) >> 5;
    int lane = threadIdx.x & 31;
    if (wid >= E) return;
    int r = __ldg(rowp + wid);
    int c = __ldg(colp + wid);
    float w = __ldg(ew + wid);
    float4 v = *(const float4*)(t + (size_t)r * DD + lane * 4);
    v.x *= w; v.y *= w; v.z *= w; v.w *= w;
    red_add_v4(acc + (size_t)c * DD + lane * 4, v);
}

// ---------------- PReLU + graph pooling ----------------
// Each warp handles 8 consecutive nodes. batch_indices are sorted, so we
// accumulate same-graph runs in registers and flush one red.v4 per change.
__global__ __launch_bounds__(256) void prelu_pool_kernel(
    const float* __restrict__ acc, const float* __restrict__ aptr,
    const int* __restrict__ batch, float* __restrict__ hout,
    float* __restrict__ hg, int N, int loff)
{
    int wid  = (blockIdx.x * blockDim.x + threadIdx.x) >> 5;
    int lane = threadIdx.x & 31;
    int n0 = wid * 8;
    if (n0 >= N) return;
    float alpha = __ldg(aptr);

    float4 run = make_float4(0.f, 0.f, 0.f, 0.f);
    int curg = -1;
    int nend = n0 + 8; if (nend > N) nend = N;

    for (int n = n0; n < nend; n++) {
        float4 v = *(const float4*)(acc + (size_t)n * DD + lane * 4);
        float4 p;
        p.x = v.x >= 0.f ? v.x : alpha * v.x;
        p.y = v.y >= 0.f ? v.y : alpha * v.y;
        p.z = v.z >= 0.f ? v.z : alpha * v.z;
        p.w = v.w >= 0.f ? v.w : alpha * v.w;
        *(float4*)(hout + (size_t)n * DD + lane * 4) = p;
        int g = __ldg(batch + n);
        if (g != curg) {
            if (curg >= 0)
                red_add_v4(hg + (size_t)curg * (3 * DD) + loff + lane * 4, run);
            curg = g;
            run = p;
        } else {
            run.x += p.x; run.y += p.y; run.z += p.z; run.w += p.w;
        }
    }
    if (curg >= 0)
        red_add_v4(hg + (size_t)curg * (3 * DD) + loff + lane * 4, run);
}

// ---------------- launch ----------------
extern "C" void kernel_launch(void* const* d_in, const int* in_sizes, int n_in,
                              void* d_out, int out_size)
{
    const float* feat  = (const float*)d_in[0];
    const float* ew    = (const float*)d_in[1];
    const float* W[3]  = {(const float*)d_in[2], (const float*)d_in[3], (const float*)d_in[4]};
    const float* a[3]  = {(const float*)d_in[5], (const float*)d_in[6], (const float*)d_in[7]};
    const int*   eidx  = (const int*)d_in[8];
    const int*   batch = (const int*)d_in[9];

    const int N = in_sizes[0] / DD;      // 40000
    const int E = in_sizes[1];           // 640000
    const int* rowp = eidx;
    const int* colp = eidx + E;

    float *t_ptr, *acc_ptr, *h_ptr;
    cudaGetSymbolAddress((void**)&t_ptr,   g_t);
    cudaGetSymbolAddress((void**)&acc_ptr, g_acc);
    cudaGetSymbolAddress((void**)&h_ptr,   g_h);

    float* h_out = (float*)d_out;                         // (N, 128)
    float* hg    = (float*)d_out + (size_t)N * DD;        // (128, 384)

    cudaFuncSetAttribute(gemm_kernel,
                         cudaFuncAttributeMaxDynamicSharedMemorySize,
                         (int)GEMM_SMEM);

    cudaStream_t s = 0;
    cudaMemsetAsync(hg, 0, (size_t)NGRAPHS * 3 * DD * sizeof(float), s);

    const int gemm_blocks    = (N + 127) / 128;
    const int scatter_blocks = (E * 32 + 255) / 256;
    const int pool_warps     = (N + 7) / 8;
    const int pool_blocks    = (pool_warps * 32 + 255) / 256;

    const float* hin = feat;
    for (int l = 0; l < 3; l++) {
        gemm_kernel<<<gemm_blocks, 256, GEMM_SMEM, s>>>(hin, W[l], t_ptr, N);
        cudaMemsetAsync(acc_ptr, 0, (size_t)N * DD * sizeof(float), s);
        scatter_kernel<<<scatter_blocks, 256, 0, s>>>(t_ptr, rowp, colp, ew, acc_ptr, E);
        float* ho = (l == 2) ? h_out : h_ptr;
        prelu_pool_kernel<<<pool_blocks, 256, 0, s>>>(acc_ptr, a[l], batch, ho, hg, N, l * DD);
        hin = h_ptr;
    }
}

// round 2
// speedup vs baseline: 1.5944x; 1.5944x over previous
#include <cuda_runtime.h>
#include <cstdint>

#define NNODES 40000
#define NEDGES_MAX 640000
#define NGRAPHS 128
#define DD 128

// ---------------- scratch (no allocations allowed) ----------------
__device__ float g_t[(size_t)NNODES * DD];    // GEMM output (pre-aggregation)
__device__ float g_h[(size_t)NNODES * DD];    // layer output (next-layer input)
__device__ int   g_deg[NNODES];
__device__ int   g_rowptr[NNODES + 1];
__device__ int   g_cursor[NNODES];
__device__ int   g_partials[256];
__device__ int   g_esrc[NEDGES_MAX];
__device__ float g_ewr[NEDGES_MAX];

// ---------------- GEMM: out[M,128] = A[M,128] @ W[128,128]^T ----------------
// BM=128, BN=128, BK=32, 256 threads, 8x8 microtile. 34KB smem -> 2 CTAs/SM.
#define LDT 132
#define BK 32
#define GEMM_SMEM (2 * BK * LDT * sizeof(float))

__global__ __launch_bounds__(256, 2) void gemm_kernel(
    const float* __restrict__ A, const float* __restrict__ W,
    float* __restrict__ out, int M)
{
    __shared__ float At[BK * LDT];   // At[k][m]
    __shared__ float Wt[BK * LDT];   // Wt[k][n]

    const int tid = threadIdx.x;
    const int rbase = blockIdx.x * 128;
    const int tx = tid & 15;   // col group
    const int ty = tid >> 4;   // row group

    float acc[8][8];
    #pragma unroll
    for (int i = 0; i < 8; i++)
        #pragma unroll
        for (int j = 0; j < 8; j++) acc[i][j] = 0.f;

    for (int kt = 0; kt < 128; kt += BK) {
        // load tiles: 128 rows x 8 k-quads = 1024 float4 per tile -> 4/thread
        #pragma unroll
        for (int rep = 0; rep < 4; rep++) {
            int idx = tid + rep * 256;   // 0..1023
            int r   = idx >> 3;          // 0..127
            int kq  = idx & 7;           // 0..7
            float4 av = make_float4(0.f, 0.f, 0.f, 0.f);
            int gr = rbase + r;
            if (gr < M) av = *(const float4*)(A + (size_t)gr * DD + kt + kq * 4);
            At[(kq * 4 + 0) * LDT + r] = av.x;
            At[(kq * 4 + 1) * LDT + r] = av.y;
            At[(kq * 4 + 2) * LDT + r] = av.z;
            At[(kq * 4 + 3) * LDT + r] = av.w;
            float4 wv = *(const float4*)(W + (size_t)r * DD + kt + kq * 4);
            Wt[(kq * 4 + 0) * LDT + r] = wv.x;
            Wt[(kq * 4 + 1) * LDT + r] = wv.y;
            Wt[(kq * 4 + 2) * LDT + r] = wv.z;
            Wt[(kq * 4 + 3) * LDT + r] = wv.w;
        }
        __syncthreads();

        #pragma unroll 8
        for (int k = 0; k < BK; k++) {
            float4 a0 = *(const float4*)&At[k * LDT + ty * 8];
            float4 a1 = *(const float4*)&At[k * LDT + ty * 8 + 4];
            float4 b0 = *(const float4*)&Wt[k * LDT + tx * 8];
            float4 b1 = *(const float4*)&Wt[k * LDT + tx * 8 + 4];
            float a[8] = {a0.x, a0.y, a0.z, a0.w, a1.x, a1.y, a1.z, a1.w};
            float b[8] = {b0.x, b0.y, b0.z, b0.w, b1.x, b1.y, b1.z, b1.w};
            #pragma unroll
            for (int i = 0; i < 8; i++)
                #pragma unroll
                for (int j = 0; j < 8; j++)
                    acc[i][j] = fmaf(a[i], b[j], acc[i][j]);
        }
        __syncthreads();
    }

    #pragma unroll
    for (int i = 0; i < 8; i++) {
        int gr = rbase + ty * 8 + i;
        if (gr < M) {
            float4 o0 = make_float4(acc[i][0], acc[i][1], acc[i][2], acc[i][3]);
            float4 o1 = make_float4(acc[i][4], acc[i][5], acc[i][6], acc[i][7]);
            *(float4*)(out + (size_t)gr * DD + tx * 8)     = o0;
            *(float4*)(out + (size_t)gr * DD + tx * 8 + 4) = o1;
        }
    }
}

// ---------------- CSR build: histogram + 2-level scan + reorder ----------------
__global__ void hist_kernel(const int* __restrict__ col, int* __restrict__ deg, int E)
{
    int e = blockIdx.x * blockDim.x + threadIdx.x;
    if (e < E) atomicAdd(&deg[col[e]], 1);
}

__global__ void block_sum_kernel(const int* __restrict__ deg, int* __restrict__ partials, int N)
{
    __shared__ int s[256];
    int i = blockIdx.x * 256 + threadIdx.x;
    s[threadIdx.x] = (i < N) ? deg[i] : 0;
    __syncthreads();
    for (int off = 128; off > 0; off >>= 1) {
        if (threadIdx.x < off) s[threadIdx.x] += s[threadIdx.x + off];
        __syncthreads();
    }
    if (threadIdx.x == 0) partials[blockIdx.x] = s[0];
}

__global__ void scan_partials_kernel(int* __restrict__ partials, int nb,
                                     int* __restrict__ rowptr, int N)
{
    __shared__ int s[256];
    int t = threadIdx.x;
    int d = (t < nb) ? partials[t] : 0;
    s[t] = d;
    __syncthreads();
    #pragma unroll
    for (int off = 1; off < 256; off <<= 1) {
        int v = (t >= off) ? s[t - off] : 0;
        __syncthreads();
        s[t] += v;
        __syncthreads();
    }
    if (t < nb) partials[t] = s[t] - d;     // exclusive
    if (t == 255) rowptr[N] = s[255];       // grand total = E
}

__global__ void chunk_scan_kernel(const int* __restrict__ deg,
                                  const int* __restrict__ partials,
                                  int* __restrict__ rowptr, int* __restrict__ cursor, int N)
{
    __shared__ int s[256];
    int t = threadIdx.x;
    int i = blockIdx.x * 256 + t;
    int d = (i < N) ? deg[i] : 0;
    s[t] = d;
    __syncthreads();
    #pragma unroll
    for (int off = 1; off < 256; off <<= 1) {
        int v = (t >= off) ? s[t - off] : 0;
        __syncthreads();
        s[t] += v;
        __syncthreads();
    }
    if (i < N) {
        int val = partials[blockIdx.x] + s[t] - d;   // exclusive global prefix
        rowptr[i] = val;
        cursor[i] = val;
    }
}

__global__ void fill_kernel(const int* __restrict__ row, const int* __restrict__ col,
                            const float* __restrict__ ew,
                            int* __restrict__ cursor,
                            int* __restrict__ esrc, float* __restrict__ ewr, int E)
{
    int e = blockIdx.x * blockDim.x + threadIdx.x;
    if (e >= E) return;
    int c = col[e];
    int p = atomicAdd(&cursor[c], 1);
    esrc[p] = row[e];
    ewr[p]  = ew[e];
}

// ---------------- fused aggregate (CSR gather) + PReLU + pool ----------------
__device__ __forceinline__ void red_add_v4(float* dst, float4 v) {
    asm volatile("red.global.add.v4.f32 [%0], {%1, %2, %3, %4};"
                 :: "l"(dst), "f"(v.x), "f"(v.y), "f"(v.z), "f"(v.w)
                 : "memory");
}

__global__ __launch_bounds__(256) void aggregate_pool_kernel(
    const float* __restrict__ t, const int* __restrict__ rowptr,
    const int* __restrict__ esrc, const float* __restrict__ ewr,
    const float* __restrict__ aptr, const int* __restrict__ batch,
    float* __restrict__ hout, float* __restrict__ hg, int N, int loff)
{
    int wid  = (blockIdx.x * blockDim.x + threadIdx.x) >> 5;
    int lane = threadIdx.x & 31;
    int n0 = wid * 4;
    if (n0 >= N) return;
    float alpha = __ldg(aptr);

    float4 run = make_float4(0.f, 0.f, 0.f, 0.f);
    int curg = -1;
    int nend = n0 + 4; if (nend > N) nend = N;

    for (int n = n0; n < nend; n++) {
        int jb = __ldg(rowptr + n);
        int je = __ldg(rowptr + n + 1);
        float4 acc = make_float4(0.f, 0.f, 0.f, 0.f);
        for (int j = jb; j < je; j++) {
            int r   = __ldg(esrc + j);
            float w = __ldg(ewr + j);
            float4 v = __ldg((const float4*)(t + (size_t)r * DD + lane * 4));
            acc.x = fmaf(v.x, w, acc.x);
            acc.y = fmaf(v.y, w, acc.y);
            acc.z = fmaf(v.z, w, acc.z);
            acc.w = fmaf(v.w, w, acc.w);
        }
        float4 p;
        p.x = acc.x >= 0.f ? acc.x : alpha * acc.x;
        p.y = acc.y >= 0.f ? acc.y : alpha * acc.y;
        p.z = acc.z >= 0.f ? acc.z : alpha * acc.z;
        p.w = acc.w >= 0.f ? acc.w : alpha * acc.w;
        *(float4*)(hout + (size_t)n * DD + lane * 4) = p;

        int g = __ldg(batch + n);
        if (g != curg) {
            if (curg >= 0)
                red_add_v4(hg + (size_t)curg * (3 * DD) + loff + lane * 4, run);
            curg = g;
            run = p;
        } else {
            run.x += p.x; run.y += p.y; run.z += p.z; run.w += p.w;
        }
    }
    if (curg >= 0)
        red_add_v4(hg + (size_t)curg * (3 * DD) + loff + lane * 4, run);
}

// ---------------- launch ----------------
extern "C" void kernel_launch(void* const* d_in, const int* in_sizes, int n_in,
                              void* d_out, int out_size)
{
    const float* feat  = (const float*)d_in[0];
    const float* ew    = (const float*)d_in[1];
    const float* W[3]  = {(const float*)d_in[2], (const float*)d_in[3], (const float*)d_in[4]};
    const float* a[3]  = {(const float*)d_in[5], (const float*)d_in[6], (const float*)d_in[7]};
    const int*   eidx  = (const int*)d_in[8];
    const int*   batch = (const int*)d_in[9];

    const int N = in_sizes[0] / DD;      // 40000
    const int E = in_sizes[1];           // 640000
    const int* rowp = eidx;
    const int* colp = eidx + E;

    float *t_ptr, *h_ptr, *ewr_ptr;
    int *deg_ptr, *rowptr_ptr, *cursor_ptr, *partials_ptr, *esrc_ptr;
    cudaGetSymbolAddress((void**)&t_ptr,       g_t);
    cudaGetSymbolAddress((void**)&h_ptr,       g_h);
    cudaGetSymbolAddress((void**)&deg_ptr,     g_deg);
    cudaGetSymbolAddress((void**)&rowptr_ptr,  g_rowptr);
    cudaGetSymbolAddress((void**)&cursor_ptr,  g_cursor);
    cudaGetSymbolAddress((void**)&partials_ptr,g_partials);
    cudaGetSymbolAddress((void**)&esrc_ptr,    g_esrc);
    cudaGetSymbolAddress((void**)&ewr_ptr,     g_ewr);

    float* h_out = (float*)d_out;                         // (N, 128)
    float* hg    = (float*)d_out + (size_t)N * DD;        // (128, 384)

    cudaStream_t s = 0;
    cudaMemsetAsync(hg, 0, (size_t)NGRAPHS * 3 * DD * sizeof(float), s);
    cudaMemsetAsync(deg_ptr, 0, (size_t)N * sizeof(int), s);

    // ---- CSR build ----
    const int nb = (N + 255) / 256;      // 157 chunks
    hist_kernel<<<(E + 255) / 256, 256, 0, s>>>(colp, deg_ptr, E);
    block_sum_kernel<<<nb, 256, 0, s>>>(deg_ptr, partials_ptr, N);
    scan_partials_kernel<<<1, 256, 0, s>>>(partials_ptr, nb, rowptr_ptr, N);
    chunk_scan_kernel<<<nb, 256, 0, s>>>(deg_ptr, partials_ptr, rowptr_ptr, cursor_ptr, N);
    fill_kernel<<<(E + 255) / 256, 256, 0, s>>>(rowp, colp, ew, cursor_ptr, esrc_ptr, ewr_ptr, E);

    // ---- layers ----
    const int gemm_blocks = (N + 127) / 128;
    const int agg_warps   = (N + 3) / 4;
    const int agg_blocks  = (agg_warps * 32 + 255) / 256;

    const float* hin = feat;
    for (int l = 0; l < 3; l++) {
        gemm_kernel<<<gemm_blocks, 256, 0, s>>>(hin, W[l], t_ptr, N);
        float* ho = (l == 2) ? h_out : h_ptr;
        aggregate_pool_kernel<<<agg_blocks, 256, 0, s>>>(
            t_ptr, rowptr_ptr, esrc_ptr, ewr_ptr, a[l], batch, ho, hg, N, l * DD);
        hin = h_ptr;
    }
}